// round 8
// baseline (speedup 1.0000x reference)
#include <cuda_runtime.h>
#include <cstdint>

#define BB 2
#define SS 2048
#define HH 32
#define HKK 8
#define DD 128
#define SINKN 128
#define REP 4
#define KKG (SINKN + SS)          // 2176 keys incl sink
#define QSCALE 0.08838834764831845f
#define NEG -1e30f

#define BQ 128
#define BK 64
#define NTQT (SS / BQ)            // 16 q tiles

// smem strides (floats); ≡4 (mod 32) -> conflict-free ldmatrix row phases
#define QSTR  132
#define KSTR  132
#define VTSTR 68
// smem float offsets
#define OFF_Q   0
#define QF      (128 * QSTR)             // 16896
#define OFF_K0  (OFF_Q + QF)
#define KF      (BK * KSTR)              // 8448
#define OFF_K1  (OFF_K0 + KF)
#define OFF_V0  (OFF_K1 + KF)
#define VTF     (DD * VTSTR)             // 8704
#define OFF_V1  (OFF_V0 + VTF)
#define SMEM_FLOATS (OFF_V1 + VTF)       // 51200 floats = 204800 B

// ---------------------------------------------------------------------------
__device__ __forceinline__ uint32_t f2tf32(float x) {
    uint32_t r;
    asm("cvt.rna.tf32.f32 %0, %1;" : "=r"(r) : "f"(x));
    return r;
}
__device__ __forceinline__ uint32_t smem_u32(const void* p) {
    uint32_t a;
    asm("{ .reg .u64 t; cvta.to.shared.u64 t, %1; cvt.u32.u64 %0, t; }" : "=r"(a) : "l"(p));
    return a;
}
__device__ __forceinline__ void mma_tf32(float c[4], const uint32_t a[4],
                                         uint32_t b0, uint32_t b1) {
    asm volatile("mma.sync.aligned.m16n8k8.row.col.f32.tf32.tf32.f32 "
                 "{%0,%1,%2,%3}, {%4,%5,%6,%7}, {%8,%9}, {%0,%1,%2,%3};"
                 : "+f"(c[0]), "+f"(c[1]), "+f"(c[2]), "+f"(c[3])
                 : "r"(a[0]), "r"(a[1]), "r"(a[2]), "r"(a[3]), "r"(b0), "r"(b1));
}
__device__ __forceinline__ void ldsm_x4(uint32_t r[4], uint32_t addr) {
    asm volatile("ldmatrix.sync.aligned.m8n8.x4.shared.b16 {%0,%1,%2,%3}, [%4];"
                 : "=r"(r[0]), "=r"(r[1]), "=r"(r[2]), "=r"(r[3]) : "r"(addr));
}
__device__ __forceinline__ void cp16(uint32_t dst, const float* src) {
    asm volatile("cp.async.cg.shared.global [%0], [%1], 16;" :: "r"(dst), "l"(src));
}
#define CP_COMMIT() asm volatile("cp.async.commit_group;" ::: "memory")
#define CP_WAIT0()  asm volatile("cp.async.wait_group 0;" ::: "memory")
#define CP_WAIT1()  asm volatile("cp.async.wait_group 1;" ::: "memory")
#define CP_WAIT2()  asm volatile("cp.async.wait_group 2;" ::: "memory")

// ---------------------------------------------------------------------------
// scratch: K roped+sink-merged [b][hk][key][128]; V^T sink-merged [b][hk][d][KKG]
// ---------------------------------------------------------------------------
__device__ float g_kc[(size_t)BB * HKK * KKG * DD];
__device__ float g_vt[(size_t)BB * HKK * DD * KKG];

__global__ void prep_k_kernel(const float* __restrict__ k,
                              const float* __restrict__ sink_k,
                              const float* __restrict__ cs,
                              const int* __restrict__ pos) {
    int tid = blockIdx.x * blockDim.x + threadIdx.x;
    const int total = BB * HKK * KKG * 64;
    if (tid >= total) return;
    int d = tid & 63;
    int r = tid >> 6;
    int kkg = r % KKG;
    int bh = r / KKG;
    int hk = bh % HKK;
    int b = bh / HKK;
    float* dst = g_kc + ((size_t)(b * HKK + hk) * KKG + kkg) * DD;
    float o1, o2;
    if (kkg < SINKN) {
        const float* src = sink_k + ((size_t)(b * SINKN + kkg) * HKK + hk) * DD;
        o1 = src[d]; o2 = src[d + 64];
    } else {
        int s = kkg - SINKN;
        int p = pos[s];
        float c = cs[p * 128 + d];
        float sn = cs[p * 128 + 64 + d];
        const float* src = k + ((size_t)(b * SS + s) * HKK + hk) * DD;
        float x1 = src[d], x2 = src[d + 64];
        o1 = x1 * c - x2 * sn;
        o2 = x2 * c + x1 * sn;
    }
    dst[d]      = __uint_as_float(f2tf32(o1));
    dst[d + 64] = __uint_as_float(f2tf32(o2));
}

// transpose V into g_vt[d][key]
__global__ void prep_vt_kernel(const float* __restrict__ v,
                               const float* __restrict__ sink_v) {
    __shared__ float ts[32][33];
    int kkt = blockIdx.x;
    int dt = blockIdx.y;
    int bh = blockIdx.z;
    int hk = bh % HKK;
    int b = bh / HKK;
    int tx = threadIdx.x;
    int ty = threadIdx.y;
#pragma unroll
    for (int i = 0; i < 4; i++) {
        int row = ty + i * 8;
        int kkg = kkt * 32 + row;
        int d = dt * 32 + tx;
        float val;
        if (kkg < SINKN)
            val = sink_v[((size_t)(b * SINKN + kkg) * HKK + hk) * DD + d];
        else
            val = v[((size_t)(b * SS + (kkg - SINKN)) * HKK + hk) * DD + d];
        ts[row][tx] = __uint_as_float(f2tf32(val));
    }
    __syncthreads();
#pragma unroll
    for (int i = 0; i < 4; i++) {
        int drow = ty + i * 8;
        int d = dt * 32 + drow;
        int kkg = kkt * 32 + tx;
        g_vt[((size_t)(b * HKK + hk) * DD + d) * KKG + kkg] = ts[tx][drow];
    }
}

// ---------------------------------------------------------------------------
// FA2-style tf32 mma.sync flash attention with ldmatrix B-fragments
// ---------------------------------------------------------------------------
extern __shared__ float smf[];

__global__ void __launch_bounds__(256, 1)
attn_kernel(const float* __restrict__ q,
            const float* __restrict__ cs,
            const int* __restrict__ pos,
            float* __restrict__ out) {
    const int tid = threadIdx.x;
    const int w = tid >> 5;
    const int lane = tid & 31;
    const int quad = lane >> 2;
    const int qla = lane & 3;

    int bid = blockIdx.x;
    int qt = (NTQT - 1) - bid / (BB * HH);
    int bh = bid % (BB * HH);
    int h = bh % HH;
    int b = bh / HH;
    int hk = h / REP;
    const int ntiles = 2 * qt + 4;
    const int qg0 = qt * BQ;

    const float* kbase = g_kc + (size_t)(b * HKK + hk) * KKG * DD;
    const float* vtbase = g_vt + (size_t)(b * HKK + hk) * DD * KKG;

    const uint32_t smb = smem_u32(smf);

    // ldmatrix per-lane offsets: lanes 0-7 matrix0 (+0 floats), 8-15 m1 (+4),
    // 16-23 m2 (+8), 24-31 m3 (+12)
    const int lrow = lane & 7;
    const int lcol = ((lane >> 3) & 1) * 4 + (lane >> 4) * 8;
    const uint32_t kLaneOff = (uint32_t)(lrow * KSTR + lcol) * 4u;
    const uint32_t vLaneOff = (uint32_t)(lrow * VTSTR + lcol) * 4u;

    // ---- prefetch K/V^T tile 0 (separate commit groups) ----
    {
#pragma unroll
        for (int i = 0; i < 8; i++) {
            int c = i * 256 + tid;
            int kr = c >> 5, kc = (c & 31) * 4;
            cp16(smb + (uint32_t)(OFF_K0 + kr * KSTR + kc) * 4, kbase + kr * DD + kc);
        }
        CP_COMMIT();
#pragma unroll
        for (int i = 0; i < 8; i++) {
            int c = i * 256 + tid;
            int vr = c >> 4, vc = (c & 15) * 4;
            cp16(smb + (uint32_t)(OFF_V0 + vr * VTSTR + vc) * 4, vtbase + (size_t)vr * KKG + vc);
        }
        CP_COMMIT();
    }

    // ---- stage Q with fused RoPE + scale ----
    for (int i = tid; i < 128 * 16; i += 256) {
        int r = i >> 4, c4 = i & 15;
        int qg = qg0 + r;
        int p = pos[qg];
        float4 cc = *(const float4*)(cs + (size_t)p * 128 + c4 * 4);
        float4 ss = *(const float4*)(cs + (size_t)p * 128 + 64 + c4 * 4);
        const float* qb = q + ((size_t)(b * SS + qg) * HH + h) * DD;
        float4 x1 = *(const float4*)(qb + c4 * 4);
        float4 x2 = *(const float4*)(qb + 64 + c4 * 4);
        float4 o1, o2;
        o1.x = (x1.x * cc.x - x2.x * ss.x) * QSCALE;
        o1.y = (x1.y * cc.y - x2.y * ss.y) * QSCALE;
        o1.z = (x1.z * cc.z - x2.z * ss.z) * QSCALE;
        o1.w = (x1.w * cc.w - x2.w * ss.w) * QSCALE;
        o2.x = (x2.x * cc.x + x1.x * ss.x) * QSCALE;
        o2.y = (x2.y * cc.y + x1.y * ss.y) * QSCALE;
        o2.z = (x2.z * cc.z + x1.z * ss.z) * QSCALE;
        o2.w = (x2.w * cc.w + x1.w * ss.w) * QSCALE;
        *(float4*)(smf + OFF_Q + r * QSTR + c4 * 4) = o1;
        *(float4*)(smf + OFF_Q + r * QSTR + 64 + c4 * 4) = o2;
    }
    __syncthreads();

    // ---- Q fragments -> registers ----
    uint32_t aq[16][4];
    {
        const float* qr0 = smf + OFF_Q + (w * 16 + quad) * QSTR;
        const float* qr1 = qr0 + 8 * QSTR;
#pragma unroll
        for (int k = 0; k < 16; k++) {
            int col = k * 8 + qla;
            aq[k][0] = f2tf32(qr0[col]);
            aq[k][1] = f2tf32(qr1[col]);
            aq[k][2] = f2tf32(qr0[col + 4]);
            aq[k][3] = f2tf32(qr1[col + 4]);
        }
    }

    float o[16][4];
#pragma unroll
    for (int n = 0; n < 16; n++) { o[n][0] = o[n][1] = o[n][2] = o[n][3] = 0.f; }
    float lsum0 = 0.f, lsum1 = 0.f;

    const int srcA = (lane & ~3) | (qla >> 1);
    const int srcB = srcA + 2;
    const bool odd = qla & 1;

    for (int t = 0; t < ntiles; t++) {
        CP_WAIT1();              // K tile ready (V may still be in flight)
        __syncthreads();
        const int cur = t & 1;
        // prefetch next tile
        if (t + 1 < ntiles) {
            const float* kb = kbase + (size_t)(t + 1) * BK * DD;
            const float* vtb = vtbase + (size_t)(t + 1) * BK;
            const uint32_t ko = (t + 1) & 1 ? OFF_K1 : OFF_K0;
            const uint32_t vo = (t + 1) & 1 ? OFF_V1 : OFF_V0;
#pragma unroll
            for (int i = 0; i < 8; i++) {
                int c = i * 256 + tid;
                int kr = c >> 5, kc = (c & 31) * 4;
                cp16(smb + (ko + kr * KSTR + kc) * 4, kb + kr * DD + kc);
            }
            CP_COMMIT();
#pragma unroll
            for (int i = 0; i < 8; i++) {
                int c = i * 256 + tid;
                int vr = c >> 4, vc = (c & 15) * 4;
                cp16(smb + (vo + vr * VTSTR + vc) * 4, vtb + (size_t)vr * KKG + vc);
            }
            CP_COMMIT();
        }
        const uint32_t kBuf = smb + (uint32_t)(cur ? OFF_K1 : OFF_K0) * 4 + kLaneOff;
        const uint32_t vBuf = smb + (uint32_t)(cur ? OFF_V1 : OFF_V0) * 4 + vLaneOff;

        // ---- S = Q @ K^T : ldmatrix.x4 per (kpair, n) ----
        float s[8][4];
#pragma unroll
        for (int n = 0; n < 8; n++) { s[n][0] = s[n][1] = s[n][2] = s[n][3] = 0.f; }
#pragma unroll
        for (int kp = 0; kp < 8; kp++) {
#pragma unroll
            for (int n = 0; n < 8; n++) {
                uint32_t r[4];
                ldsm_x4(r, kBuf + (uint32_t)(n * 8 * KSTR + kp * 16) * 4);
                mma_tf32(s[n], aq[2 * kp], r[0], r[1]);
                mma_tf32(s[n], aq[2 * kp + 1], r[2], r[3]);
            }
        }

        // ---- causal mask (only last two tiles intersect diagonal) ----
        if (t >= ntiles - 2) {
            int rb0 = qg0 + w * 16 + quad + SINKN;
            int rb1 = rb0 + 8;
#pragma unroll
            for (int n = 0; n < 8; n++) {
                int kg = t * BK + n * 8 + 2 * qla;
                if (kg > rb0) s[n][0] = NEG;
                if (kg + 1 > rb0) s[n][1] = NEG;
                if (kg > rb1) s[n][2] = NEG;
                if (kg + 1 > rb1) s[n][3] = NEG;
            }
        }

        // ---- P = exp(S), row sums ----
#pragma unroll
        for (int n = 0; n < 8; n++) {
            s[n][0] = __expf(s[n][0]);
            s[n][1] = __expf(s[n][1]);
            s[n][2] = __expf(s[n][2]);
            s[n][3] = __expf(s[n][3]);
            lsum0 += s[n][0] + s[n][1];
            lsum1 += s[n][2] + s[n][3];
        }

        // ---- V tile ready (loads overlapped with S-phase) ----
        if (t + 1 < ntiles) { CP_WAIT2(); } else { CP_WAIT0(); }
        __syncthreads();

        // ---- O += P @ V ----
#pragma unroll
        for (int kkp = 0; kkp < 4; kkp++) {
            uint32_t paLo[4], paHi[4];
#pragma unroll
            for (int half = 0; half < 2; half++) {
                int kk = 2 * kkp + half;
                float v0a = __shfl_sync(0xffffffffu, s[kk][0], srcA);
                float v1a = __shfl_sync(0xffffffffu, s[kk][1], srcA);
                float v2a = __shfl_sync(0xffffffffu, s[kk][2], srcA);
                float v3a = __shfl_sync(0xffffffffu, s[kk][3], srcA);
                float v0b = __shfl_sync(0xffffffffu, s[kk][0], srcB);
                float v1b = __shfl_sync(0xffffffffu, s[kk][1], srcB);
                float v2b = __shfl_sync(0xffffffffu, s[kk][2], srcB);
                float v3b = __shfl_sync(0xffffffffu, s[kk][3], srcB);
                uint32_t* pa = half ? paHi : paLo;
                pa[0] = f2tf32(odd ? v1a : v0a);
                pa[1] = f2tf32(odd ? v3a : v2a);
                pa[2] = f2tf32(odd ? v1b : v0b);
                pa[3] = f2tf32(odd ? v3b : v2b);
            }
#pragma unroll
            for (int n = 0; n < 16; n++) {
                uint32_t r[4];
                ldsm_x4(r, vBuf + (uint32_t)(n * 8 * VTSTR + kkp * 16) * 4);
                mma_tf32(o[n], paLo, r[0], r[1]);
                mma_tf32(o[n], paHi, r[2], r[3]);
            }
        }
    }

    // ---- row-sum reduction across quad lanes ----
    lsum0 += __shfl_xor_sync(0xffffffffu, lsum0, 1);
    lsum0 += __shfl_xor_sync(0xffffffffu, lsum0, 2);
    lsum1 += __shfl_xor_sync(0xffffffffu, lsum1, 1);
    lsum1 += __shfl_xor_sync(0xffffffffu, lsum1, 2);
    float inv0 = 1.0f / lsum0;
    float inv1 = 1.0f / lsum1;

    // ---- writeback ----
    int row0 = qg0 + w * 16 + quad;
    int row1 = row0 + 8;
    float* ob0 = out + ((size_t)(b * SS + row0) * HH + h) * DD;
    float* ob1 = out + ((size_t)(b * SS + row1) * HH + h) * DD;
#pragma unroll
    for (int n = 0; n < 16; n++) {
        int d = n * 8 + 2 * qla;
        float2 r0 = { o[n][0] * inv0, o[n][1] * inv0 };
        float2 r1 = { o[n][2] * inv1, o[n][3] * inv1 };
        *(float2*)(ob0 + d) = r0;
        *(float2*)(ob1 + d) = r1;
    }
}

// ---------------------------------------------------------------------------
extern "C" void kernel_launch(void* const* d_in, const int* in_sizes, int n_in,
                              void* d_out, int out_size) {
    const float* q = (const float*)d_in[0];
    const float* k = (const float*)d_in[1];
    const float* v = (const float*)d_in[2];
    const float* sink_k = (const float*)d_in[3];
    const float* sink_v = (const float*)d_in[4];
    const float* cscache = (const float*)d_in[5];
    const int* pos = (const int*)d_in[6];
    float* out = (float*)d_out;

    {
        int total = BB * HKK * KKG * 64;
        prep_k_kernel<<<(total + 255) / 256, 256>>>(k, sink_k, cscache, pos);
    }
    {
        dim3 grid(KKG / 32, DD / 32, BB * HKK);
        dim3 block(32, 8);
        prep_vt_kernel<<<grid, block>>>(v, sink_v);
    }
    {
        const int smem_bytes = SMEM_FLOATS * (int)sizeof(float);
        cudaFuncSetAttribute(attn_kernel,
                             cudaFuncAttributeMaxDynamicSharedMemorySize, smem_bytes);
        int grid = NTQT * BB * HH;   // 1024
        attn_kernel<<<grid, 256, smem_bytes>>>(q, cscache, pos, out);
    }
}